// round 12
// baseline (speedup 1.0000x reference)
#include <cuda_runtime.h>
#include <cuda_fp16.h>
#include <math.h>
#include <stdint.h>

#define T_    128
#define BSZ   1024
#define IN_   75
#define H_    128
#define G4_   512
#define OUT_  256
#define MDEC  (128*75)
#define EPS_  1e-5f
#define RBLK  32
#define RTHR  256

typedef unsigned long long ull;

// ---------------- device scratch ----------------
__device__ __half g_XT  [(size_t)T_*G4_*BSZ];  // (T, 4H, B) fp16 gate pre-activations
__device__ __half g_xbk [(size_t)T_*BSZ*128];  // (T, B, 128) fp16 padded input, k-contig
__device__ __half g_hbk [(size_t)T_*BSZ*128];  // (T, B, 128) fp16 hs0 transposed, k-contig
__device__ __half g_Wt  [(size_t)G4_*128];     // (512, 128) fp16 Wih^T k-contig
__device__ __half g_WtR [(size_t)G4_*128];     // (512, 128) fp16 Whh^T k-contig
__device__ float  g_hs0T[(size_t)T_*H_*BSZ];
__device__ float  g_hs1T[(size_t)T_*H_*BSZ];
__device__ __half g_h16 [(size_t)2*BSZ*H_];    // ping-pong fp16 recurrent h, (p, B, H) k-contig
__device__ float  g_xsA [(size_t)T_*G4_];
__device__ float  g_xsB [(size_t)T_*G4_];
__device__ float  g_embT[(size_t)OUT_*BSZ];
__device__ unsigned g_barArr;

__global__ void reset_bar_k() { g_barArr = 0u; }

__device__ __forceinline__ float tanh_fast(float x) {
    float y; asm("tanh.approx.f32 %0, %1;" : "=f"(y) : "f"(x)); return y;
}
__device__ __forceinline__ float sigm(float x) {
    return fmaf(0.5f, tanh_fast(0.5f * x), 0.5f);
}
__device__ __forceinline__ ull pack2(float lo, float hi) {
    ull r; asm("mov.b64 %0, {%1, %2};" : "=l"(r) : "f"(lo), "f"(hi)); return r;
}
__device__ __forceinline__ void unpack2(ull v, float& lo, float& hi) {
    asm("mov.b64 {%0, %1}, %2;" : "=f"(lo), "=f"(hi) : "l"(v));
}
__device__ __forceinline__ void fma2(ull& d, ull a, ull b) {
    asm("fma.rn.f32x2 %0, %1, %2, %0;" : "+l"(d) : "l"(a), "l"(b));
}
__device__ __forceinline__ void mma16816(float* c, const uint32_t* a, const uint32_t* b) {
    asm volatile(
        "mma.sync.aligned.m16n8k16.row.col.f32.f16.f16.f32 "
        "{%0,%1,%2,%3}, {%4,%5,%6,%7}, {%8,%9}, {%0,%1,%2,%3};"
        : "+f"(c[0]), "+f"(c[1]), "+f"(c[2]), "+f"(c[3])
        : "r"(a[0]), "r"(a[1]), "r"(a[2]), "r"(a[3]), "r"(b[0]), "r"(b[1]));
}

// ================= HMMA fp16 FF GEMM (unchanged, proven) =================
#define SROW 136

__global__ __launch_bounds__(256) void hmma_gemm(
    const __half* __restrict__ Wt,
    const __half* __restrict__ Xbk,
    __half* __restrict__ XT)
{
    extern __shared__ __half sm[];
    __half* As = sm;
    __half* Bs = sm + 128 * SROW;

    const int t  = blockIdx.z;
    const int n0 = blockIdx.y * 128;
    const int b0 = blockIdx.x * 128;
    const int tid = threadIdx.x;
    const int wid = tid >> 5, lane = tid & 31;
    const int wm = wid >> 1;
    const int wn = wid & 1;

    {
        const float4* Ag = (const float4*)(Wt + (size_t)n0 * 128);
        const float4* Bg = (const float4*)(Xbk + ((size_t)t * BSZ + b0) * 128);
#pragma unroll
        for (int it = 0; it < 8; it++) {
            int i = tid + 256 * it;
            int r = i >> 4, c8 = (i & 15) * 8;
            *(float4*)&As[r * SROW + c8] = Ag[i];
            *(float4*)&Bs[r * SROW + c8] = Bg[i];
        }
    }
    __syncthreads();

    float acc[2][8][4];
#pragma unroll
    for (int mt = 0; mt < 2; mt++)
#pragma unroll
        for (int nt = 0; nt < 8; nt++)
#pragma unroll
            for (int e = 0; e < 4; e++) acc[mt][nt][e] = 0.f;

    const int fr = lane >> 2;
    const int kp = (lane & 3) * 2;

#pragma unroll
    for (int ks = 0; ks < 8; ks++) {
        const int k0 = ks * 16;
        uint32_t a[2][4];
#pragma unroll
        for (int mt = 0; mt < 2; mt++) {
            const int mr = wm * 32 + mt * 16;
            a[mt][0] = *(const uint32_t*)&As[(mr + fr)     * SROW + k0 + kp];
            a[mt][1] = *(const uint32_t*)&As[(mr + fr + 8) * SROW + k0 + kp];
            a[mt][2] = *(const uint32_t*)&As[(mr + fr)     * SROW + k0 + kp + 8];
            a[mt][3] = *(const uint32_t*)&As[(mr + fr + 8) * SROW + k0 + kp + 8];
        }
#pragma unroll
        for (int nt = 0; nt < 8; nt++) {
            const int bc = wn * 64 + nt * 8 + fr;
            uint32_t b[2];
            b[0] = *(const uint32_t*)&Bs[bc * SROW + k0 + kp];
            b[1] = *(const uint32_t*)&Bs[bc * SROW + k0 + kp + 8];
            mma16816(acc[0][nt], a[0], b);
            mma16816(acc[1][nt], a[1], b);
        }
    }

#pragma unroll
    for (int mt = 0; mt < 2; mt++) {
        const int n = n0 + wm * 32 + mt * 16 + fr;
        __half* R0 = XT + ((size_t)t * G4_ + n)     * BSZ + b0;
        __half* R1 = XT + ((size_t)t * G4_ + n + 8) * BSZ + b0;
#pragma unroll
        for (int nt = 0; nt < 8; nt++) {
            const int bcol = wn * 64 + nt * 8 + (lane & 3) * 2;
            *(__half2*)&R0[bcol] = __floats2half2_rn(acc[mt][nt][0], acc[mt][nt][1]);
            *(__half2*)&R1[bcol] = __floats2half2_rn(acc[mt][nt][2], acc[mt][nt][3]);
        }
    }
}

// ---------------- operand prep kernels ----------------
__global__ __launch_bounds__(256) void w_to_t(const float* __restrict__ W,
                                              __half* __restrict__ Wt, int K)
{
    int i = blockIdx.x * 256 + threadIdx.x;
    int n = i >> 7, k = i & 127;
    Wt[i] = __float2half(k < K ? W[(size_t)k * G4_ + n] : 0.f);
}

__global__ __launch_bounds__(256) void x_to_bk(const float* __restrict__ seq,
                                               __half* __restrict__ xbk)
{
    int t = blockIdx.y;
    size_t i = (size_t)blockIdx.x * 256 + threadIdx.x;
    int b = (int)(i >> 7), k = (int)(i & 127);
    float v = (k < IN_) ? seq[((size_t)b * T_ + t) * IN_ + k] : 0.f;
    xbk[(size_t)t * BSZ * 128 + i] = __float2half(v);
}

__global__ __launch_bounds__(256) void h_to_bk(const float* __restrict__ hsT,
                                               __half* __restrict__ hbk)
{
    int t = blockIdx.z;
    int h0 = blockIdx.y * 32;
    int b0 = blockIdx.x * 32;
    __shared__ float sm[32][33];
    int tid = threadIdx.x;
    int lx = tid & 31, ly = tid >> 5;
#pragma unroll
    for (int i = 0; i < 4; i++) {
        int h = h0 + ly + i * 8;
        sm[ly + i * 8][lx] = hsT[((size_t)t * H_ + h) * BSZ + b0 + lx];
    }
    __syncthreads();
#pragma unroll
    for (int i = 0; i < 4; i++) {
        int b = b0 + ly + i * 8;
        hbk[((size_t)t * BSZ + b) * 128 + h0 + lx] = __float2half(sm[lx][ly + i * 8]);
    }
}

// ---------------- TN SGEMM 128x128 FFMA2 (fc + decoder, fp32) ----------------
__global__ __launch_bounds__(256) void tn_gemm128(const float* __restrict__ W,
                                                  const float* __restrict__ A,
                                                  float* __restrict__ C,
                                                  int K, int N, int Bd,
                                                  long long strideA, long long strideC,
                                                  const float* __restrict__ bias_n,
                                                  const float* __restrict__ bias_b)
{
    A += (size_t)blockIdx.z * strideA;
    C += (size_t)blockIdx.z * strideC;
    const int n0 = blockIdx.y * 128;
    const int b0 = blockIdx.x * 128;

    __shared__ float Ws[16][128];
    __shared__ float As[16][128];

    const int tid = threadIdx.x;
    const int lr = tid / 32;
    const int lc = (tid % 32) * 4;
    const int tx = tid % 16;
    const int ty = tid / 16;

    ull accP[8][4];
#pragma unroll
    for (int i = 0; i < 8; i++)
#pragma unroll
        for (int jp = 0; jp < 4; jp++) accP[i][jp] = 0ull;

    for (int k0 = 0; k0 < K; k0 += 16) {
#pragma unroll
        for (int rr = 0; rr < 2; rr++) {
            const int krow = k0 + lr + rr * 8;
            float4 wv = make_float4(0.f, 0.f, 0.f, 0.f);
            float4 av = make_float4(0.f, 0.f, 0.f, 0.f);
            if (krow < K) {
                wv = *(const float4*)&W[(size_t)krow * N  + n0 + lc];
                av = *(const float4*)&A[(size_t)krow * Bd + b0 + lc];
            }
            *(float4*)&Ws[lr + rr * 8][lc] = wv;
            *(float4*)&As[lr + rr * 8][lc] = av;
        }
        __syncthreads();
#pragma unroll
        for (int kk = 0; kk < 16; kk++) {
            float a[8];
            float4 bq0 = *(const float4*)&As[kk][tx * 8];
            float4 bq1 = *(const float4*)&As[kk][tx * 8 + 4];
            *(float4*)&a[0] = *(const float4*)&Ws[kk][ty * 8];
            *(float4*)&a[4] = *(const float4*)&Ws[kk][ty * 8 + 4];
            ull bp[4];
            bp[0] = pack2(bq0.x, bq0.y);
            bp[1] = pack2(bq0.z, bq0.w);
            bp[2] = pack2(bq1.x, bq1.y);
            bp[3] = pack2(bq1.z, bq1.w);
#pragma unroll
            for (int i = 0; i < 8; i++) {
                const ull ad = pack2(a[i], a[i]);
#pragma unroll
                for (int jp = 0; jp < 4; jp++) fma2(accP[i][jp], ad, bp[jp]);
            }
        }
        __syncthreads();
    }

#pragma unroll
    for (int i = 0; i < 8; i++) {
        const int n = n0 + ty * 8 + i;
        const float bn = bias_n ? bias_n[n] : 0.f;
        float v[8];
#pragma unroll
        for (int jp = 0; jp < 4; jp++) unpack2(accP[i][jp], v[2 * jp], v[2 * jp + 1]);
        float4 o0, o1;
        o0.x = v[0] + bn; o0.y = v[1] + bn; o0.z = v[2] + bn; o0.w = v[3] + bn;
        o1.x = v[4] + bn; o1.y = v[5] + bn; o1.z = v[6] + bn; o1.w = v[7] + bn;
        if (bias_b) {
            const int bb = b0 + tx * 8;
            o0.x += bias_b[bb + 0]; o0.y += bias_b[bb + 1];
            o0.z += bias_b[bb + 2]; o0.w += bias_b[bb + 3];
            o1.x += bias_b[bb + 4]; o1.y += bias_b[bb + 5];
            o1.z += bias_b[bb + 6]; o1.w += bias_b[bb + 7];
        }
        *(float4*)&C[(size_t)n * Bd + b0 + tx * 8]     = o0;
        *(float4*)&C[(size_t)n * Bd + b0 + tx * 8 + 4] = o1;
    }
}

// ---------------- per-(t,n) BN stats: one WARP per column, uint4 loads ----------------
__global__ __launch_bounds__(256) void x_stats(const __half* __restrict__ XT,
                                               const float* __restrict__ gih,
                                               const float* __restrict__ bih,
                                               const float* __restrict__ bgate,
                                               const float* __restrict__ bhh,
                                               float* __restrict__ xsA,
                                               float* __restrict__ xsB)
{
    const int wid = threadIdx.x >> 5, lane = threadIdx.x & 31;
    const size_t idx = (size_t)blockIdx.x * 8 + wid;
    const uint4* col = (const uint4*)(XT + idx * BSZ);
    float s = 0.f, q = 0.f;
#pragma unroll
    for (int i = 0; i < 4; i++) {
        uint4 v = col[lane + 32 * i];
        const __half2* hp = (const __half2*)&v;
#pragma unroll
        for (int j = 0; j < 4; j++) {
            float2 f = __half22float2(hp[j]);
            s += f.x + f.y;
            q += f.x * f.x + f.y * f.y;
        }
    }
#pragma unroll
    for (int o = 16; o > 0; o >>= 1) {
        s += __shfl_down_sync(0xffffffffu, s, o);
        q += __shfl_down_sync(0xffffffffu, q, o);
    }
    if (lane == 0) {
        float m = s * (1.f / BSZ);
        float var = q * (1.f / BSZ) - m * m;
        float r = rsqrtf(var + EPS_);
        int n = (int)(idx & (G4_ - 1));
        xsA[idx] = gih[n] * r;
        xsB[idx] = bih[n] - gih[n] * r * m + bgate[n] + bhh[n];
    }
}

// ---------------- persistent BN-LSTM layer: 32 blocks, HMMA recurrent GEMM ----------------
// Block u owns hidden {4u..4u+3} -> 16 gate rows r=4q+v (global col 128q+4u+v), ALL batch.
// A (Whh^T fp16) lives in registers for the whole kernel. h ping-pong (p,B,H) fp16 k-contig.
__global__ __launch_bounds__(RTHR, 1) void bnlstm32(
    const __half* __restrict__ XT,
    const float* __restrict__ xsA,
    const float* __restrict__ xsB,
    const __half* __restrict__ WtR,
    const float* __restrict__ ghh,
    const float* __restrict__ gc,
    const float* __restrict__ bc,
    float* __restrict__ hsOut,
    __half* __restrict__ h16)
{
    const int u = blockIdx.x;
    const int tid = threadIdx.x;
    const int w = tid >> 5;
    const int lane = tid & 31;
    const int fr = lane >> 2, tg = lane & 3, kp = tg * 2;
    const int wbase = w * 128;

    __shared__ float wstat[8][16][2];
    __shared__ float cstat[8][4][2];
    __shared__ float gcoef[16][2];
    __shared__ float xcoef[16][2];
    __shared__ float ccoef[4][2];
    __shared__ float ghh_s[16];
    __shared__ float gcv_s[4], bcv_s[4];

    if (tid < 16) ghh_s[tid] = ghh[((tid >> 2) << 7) + 4 * u + (tid & 3)];
    if (tid < 4)  { gcv_s[tid] = gc[4 * u + tid]; bcv_s[tid] = bc[4 * u + tid]; }

    // A fragments: rows fr (n_lo) and fr+8 (n_hi), all 8 k-steps
    const int n_lo = ((fr >> 2) << 7) + 4 * u + (fr & 3);
    const int n_hi = (((fr + 8) >> 2) << 7) + 4 * u + (fr & 3);
    uint32_t Afrag[8][4];
#pragma unroll
    for (int ks = 0; ks < 8; ks++) {
        Afrag[ks][0] = *(const uint32_t*)&WtR[n_lo * 128 + 16 * ks + kp];
        Afrag[ks][1] = *(const uint32_t*)&WtR[n_hi * 128 + 16 * ks + kp];
        Afrag[ks][2] = *(const uint32_t*)&WtR[n_lo * 128 + 16 * ks + kp + 8];
        Afrag[ks][3] = *(const uint32_t*)&WtR[n_hi * 128 + 16 * ks + kp + 8];
    }
    __syncthreads();

    float cst[16][2];                  // cell state (only fr<4 lanes meaningful)
#pragma unroll
    for (int nt = 0; nt < 16; nt++) { cst[nt][0] = 0.f; cst[nt][1] = 0.f; }

    unsigned barTarget = 0;

    for (int t = 0; t < T_; t++) {
        float C[16][4];

        if (t > 0) {
            const __half* hp = h16 + (size_t)((t - 1) & 1) * BSZ * H_;
            float s_lo = 0.f, q_lo = 0.f, s_hi = 0.f, q_hi = 0.f;
#pragma unroll
            for (int nt = 0; nt < 16; nt++) {
                const int bB = wbase + nt * 8 + fr;
                C[nt][0] = C[nt][1] = C[nt][2] = C[nt][3] = 0.f;
#pragma unroll
                for (int ks = 0; ks < 8; ks++) {
                    uint32_t bfr[2];
                    bfr[0] = *(const uint32_t*)&hp[(size_t)bB * H_ + 16 * ks + kp];
                    bfr[1] = *(const uint32_t*)&hp[(size_t)bB * H_ + 16 * ks + kp + 8];
                    mma16816(C[nt], Afrag[ks], bfr);
                }
                s_lo += C[nt][0] + C[nt][1];
                q_lo += C[nt][0] * C[nt][0] + C[nt][1] * C[nt][1];
                s_hi += C[nt][2] + C[nt][3];
                q_hi += C[nt][2] * C[nt][2] + C[nt][3] * C[nt][3];
            }
#pragma unroll
            for (int o = 1; o <= 2; o <<= 1) {
                s_lo += __shfl_xor_sync(0xffffffffu, s_lo, o);
                q_lo += __shfl_xor_sync(0xffffffffu, q_lo, o);
                s_hi += __shfl_xor_sync(0xffffffffu, s_hi, o);
                q_hi += __shfl_xor_sync(0xffffffffu, q_hi, o);
            }
            if (tg == 0) {
                wstat[w][fr][0] = s_lo;     wstat[w][fr][1] = q_lo;
                wstat[w][fr + 8][0] = s_hi; wstat[w][fr + 8][1] = q_hi;
            }
            __syncthreads();
            if (tid < 16) {
                float S = 0.f, Q = 0.f;
#pragma unroll
                for (int ww = 0; ww < 8; ww++) { S += wstat[ww][tid][0]; Q += wstat[ww][tid][1]; }
                const float m = S * (1.f / BSZ);
                const float var = Q * (1.f / BSZ) - m * m;
                gcoef[tid][0] = ghh_s[tid] * rsqrtf(var + EPS_);
                gcoef[tid][1] = m;
                const int n = ((tid >> 2) << 7) + 4 * u + (tid & 3);
                xcoef[tid][0] = xsA[t * G4_ + n];
                xcoef[tid][1] = xsB[t * G4_ + n];
            }
            __syncthreads();
        } else {
            if (tid < 16) {
                const int n = ((tid >> 2) << 7) + 4 * u + (tid & 3);
                gcoef[tid][0] = 0.f; gcoef[tid][1] = 0.f;
                xcoef[tid][0] = xsA[n]; xcoef[tid][1] = xsB[n];
            }
            __syncthreads();
#pragma unroll
            for (int nt = 0; nt < 16; nt++)
                C[nt][0] = C[nt][1] = C[nt][2] = C[nt][3] = 0.f;
        }

        // pointwise: gates + cell update (i*tanh(g) computed in fr>=4 half, shuffled over)
        const __half* Xt = XT + (size_t)t * G4_ * BSZ;
        const float galo = gcoef[fr][0],     gmlo = gcoef[fr][1];
        const float gahi = gcoef[fr + 8][0], gmhi = gcoef[fr + 8][1];
        const float xalo = xcoef[fr][0],     xblo = xcoef[fr][1];
        const float xahi = xcoef[fr + 8][0], xbhi = xcoef[fr + 8][1];

        float csacc = 0.f, cqacc = 0.f;
#pragma unroll
        for (int nt = 0; nt < 16; nt++) {
            const int bb = wbase + nt * 8 + tg * 2;
            float2 xlo = __half22float2(*(const __half2*)&Xt[(size_t)n_lo * BSZ + bb]);
            float2 xhi = __half22float2(*(const __half2*)&Xt[(size_t)n_hi * BSZ + bb]);
            float glo0 = fmaf(xalo, xlo.x, xblo) + galo * (C[nt][0] - gmlo);
            float glo1 = fmaf(xalo, xlo.y, xblo) + galo * (C[nt][1] - gmlo);
            float ghi0 = fmaf(xahi, xhi.x, xbhi) + gahi * (C[nt][2] - gmhi);
            float ghi1 = fmaf(xahi, xhi.y, xbhi) + gahi * (C[nt][3] - gmhi);
            // fr>=4: glo = i-gate, ghi = g-gate
            float ig0 = sigm(glo0) * tanh_fast(ghi0);
            float ig1 = sigm(glo1) * tanh_fast(ghi1);
            float rg0 = __shfl_xor_sync(0xffffffffu, ig0, 16);
            float rg1 = __shfl_xor_sync(0xffffffffu, ig1, 16);
            if (fr < 4) {
                // glo = f-gate, ghi = o-gate
                float c0 = fmaf(sigm(glo0), cst[nt][0], rg0);
                float c1 = fmaf(sigm(glo1), cst[nt][1], rg1);
                cst[nt][0] = c0; cst[nt][1] = c1;
                csacc += c0 + c1;
                cqacc += c0 * c0 + c1 * c1;
                C[nt][2] = sigm(ghi0);     // keep sigm(o)
                C[nt][3] = sigm(ghi1);
            }
        }

        // cell BN stats (block-local over all B)
#pragma unroll
        for (int o = 1; o <= 2; o <<= 1) {
            csacc += __shfl_xor_sync(0xffffffffu, csacc, o);
            cqacc += __shfl_xor_sync(0xffffffffu, cqacc, o);
        }
        if (fr < 4 && tg == 0) { cstat[w][fr][0] = csacc; cstat[w][fr][1] = cqacc; }
        __syncthreads();
        if (tid < 4) {
            float S = 0.f, Q = 0.f;
#pragma unroll
            for (int ww = 0; ww < 8; ww++) { S += cstat[ww][tid][0]; Q += cstat[ww][tid][1]; }
            const float mc = S * (1.f / BSZ);
            const float rc = rsqrtf(Q * (1.f / BSZ) - mc * mc + EPS_);
            const float rcg = gcv_s[tid] * rc;
            ccoef[tid][0] = rcg;
            ccoef[tid][1] = bcv_s[tid] - rcg * mc;
        }
        __syncthreads();

        if (fr < 4) {
            const float rcg = ccoef[fr][0], off = ccoef[fr][1];
            const int jj = 4 * u + fr;
            __half* hw = h16 + (size_t)(t & 1) * BSZ * H_;
            float* ho = hsOut + ((size_t)t * H_ + jj) * BSZ;
#pragma unroll
            for (int nt = 0; nt < 16; nt++) {
                const int bb = wbase + nt * 8 + tg * 2;
                float h0 = C[nt][2] * tanh_fast(fmaf(rcg, cst[nt][0], off));
                float h1 = C[nt][3] * tanh_fast(fmaf(rcg, cst[nt][1], off));
                hw[(size_t)bb * H_ + jj]       = __float2half(h0);
                hw[(size_t)(bb + 1) * H_ + jj] = __float2half(h1);
                *(float2*)&ho[bb] = make_float2(h0, h1);
            }
        }

        if (t < T_ - 1) {
            __syncthreads();
            barTarget += RBLK;
            if (tid == 0) {
                __threadfence();
                atomicAdd(&g_barArr, 1u);
                while (*((volatile unsigned*)&g_barArr) < barTarget) __nanosleep(32);
                __threadfence();
            }
            __syncthreads();
        }
    }
}

// ---------------- launch ----------------
extern "C" void kernel_launch(void* const* d_in, const int* in_sizes, int n_in,
                              void* d_out, int out_size)
{
    const float* seq  = (const float*)d_in[0];
    const float* Wih0 = (const float*)d_in[1];
    const float* Whh0 = (const float*)d_in[2];
    const float* b0   = (const float*)d_in[3];
    const float* gih0 = (const float*)d_in[4];
    const float* bih0 = (const float*)d_in[5];
    const float* ghh0 = (const float*)d_in[6];
    const float* bhh0 = (const float*)d_in[7];
    const float* gc0  = (const float*)d_in[8];
    const float* bc0  = (const float*)d_in[9];
    const float* Wih1 = (const float*)d_in[10];
    const float* Whh1 = (const float*)d_in[11];
    const float* b1   = (const float*)d_in[12];
    const float* gih1 = (const float*)d_in[13];
    const float* bih1 = (const float*)d_in[14];
    const float* ghh1 = (const float*)d_in[15];
    const float* bhh1 = (const float*)d_in[16];
    const float* gc1  = (const float*)d_in[17];
    const float* bc1  = (const float*)d_in[18];
    const float* fcw  = (const float*)d_in[19];
    const float* fcb  = (const float*)d_in[20];
    const float* decw = (const float*)d_in[21];
    const float* decb = (const float*)d_in[22];
    float* out = (float*)d_out;
    (void)in_sizes; (void)n_in; (void)out_size;

    __half *XT, *xbk, *hbk, *Wt, *WtR, *h16;
    float *hs0T, *hs1T, *xsA, *xsB, *embT;
    cudaGetSymbolAddress((void**)&XT,   g_XT);
    cudaGetSymbolAddress((void**)&xbk,  g_xbk);
    cudaGetSymbolAddress((void**)&hbk,  g_hbk);
    cudaGetSymbolAddress((void**)&Wt,   g_Wt);
    cudaGetSymbolAddress((void**)&WtR,  g_WtR);
    cudaGetSymbolAddress((void**)&h16,  g_h16);
    cudaGetSymbolAddress((void**)&hs0T, g_hs0T);
    cudaGetSymbolAddress((void**)&hs1T, g_hs1T);
    cudaGetSymbolAddress((void**)&xsA,  g_xsA);
    cudaGetSymbolAddress((void**)&xsB,  g_xsB);
    cudaGetSymbolAddress((void**)&embT, g_embT);

    const int HMMA_SMEM = 2 * 128 * SROW * (int)sizeof(__half);
    static int attr_set = 0;
    if (!attr_set) {
        cudaFuncSetAttribute(hmma_gemm, cudaFuncAttributeMaxDynamicSharedMemorySize, HMMA_SMEM);
        attr_set = 1;
    }

    // ---- layer 0 ----
    x_to_bk<<<dim3(BSZ * 128 / 256, T_), 256>>>(seq, xbk);
    w_to_t<<<G4_ * 128 / 256, 256>>>(Wih0, Wt, IN_);
    w_to_t<<<G4_ * 128 / 256, 256>>>(Whh0, WtR, H_);
    hmma_gemm<<<dim3(BSZ / 128, G4_ / 128, T_), 256, HMMA_SMEM>>>(Wt, xbk, XT);
    x_stats<<<T_ * G4_ / 8, 256>>>(XT, gih0, bih0, b0, bhh0, xsA, xsB);
    reset_bar_k<<<1, 1>>>();
    bnlstm32<<<RBLK, RTHR>>>(XT, xsA, xsB, WtR, ghh0, gc0, bc0, hs0T, h16);

    // ---- layer 1 ----
    h_to_bk<<<dim3(BSZ / 32, H_ / 32, T_), 256>>>(hs0T, hbk);
    w_to_t<<<G4_ * 128 / 256, 256>>>(Wih1, Wt, H_);
    w_to_t<<<G4_ * 128 / 256, 256>>>(Whh1, WtR, H_);
    hmma_gemm<<<dim3(BSZ / 128, G4_ / 128, T_), 256, HMMA_SMEM>>>(Wt, hbk, XT);
    x_stats<<<T_ * G4_ / 8, 256>>>(XT, gih1, bih1, b1, bhh1, xsA, xsB);
    reset_bar_k<<<1, 1>>>();
    bnlstm32<<<RBLK, RTHR>>>(XT, xsA, xsB, WtR, ghh1, gc1, bc1, hs1T, h16);

    // ---- head ----
    tn_gemm128<<<dim3(BSZ / 128, OUT_ / 128, 1), 256>>>(fcw, hs1T + (size_t)(T_ - 1) * H_ * BSZ,
                                                        embT, H_, OUT_, BSZ,
                                                        0, 0, fcb, nullptr);
    tn_gemm128<<<dim3(MDEC / 128, BSZ / 128, 1), 256>>>(embT, decw, out, OUT_, BSZ, MDEC,
                                                        0, 0, nullptr, decb);
}

// round 13
// speedup vs baseline: 1.6450x; 1.6450x over previous
#include <cuda_runtime.h>
#include <cuda_fp16.h>
#include <math.h>
#include <stdint.h>

#define T_    128
#define BSZ   1024
#define IN_   75
#define H_    128
#define G4_   512
#define OUT_  256
#define MDEC  (128*75)
#define EPS_  1e-5f
#define NBLK  128
#define NTHR  512

typedef unsigned long long ull;

// ---------------- device scratch ----------------
__device__ __half g_XT  [(size_t)T_*G4_*BSZ];  // (T, 4H, B) fp16 gate pre-activations
__device__ __half g_xbk [(size_t)T_*BSZ*128];  // (T, B, 128) fp16 padded input, k-contig
__device__ __half g_hbk [(size_t)T_*BSZ*128];  // (T, B, 128) fp16 hs0 transposed, k-contig
__device__ __half g_Wt  [(size_t)G4_*128];     // (512, 128) fp16 W^T k-contig
__device__ float  g_hs0T[(size_t)T_*H_*BSZ];
__device__ float  g_hs1T[(size_t)T_*H_*BSZ];
__device__ __half g_h16 [(size_t)2*H_*BSZ];    // ping-pong fp16 recurrent h
__device__ float  g_xsA [(size_t)T_*G4_];
__device__ float  g_xsB [(size_t)T_*G4_];
__device__ __half g_emb16[(size_t)BSZ*OUT_];   // fc output (B, 256) k-contig fp16
__device__ __half g_fw16 [(size_t)OUT_*H_];    // fcw^T (256, 128) fp16
__device__ __half g_dw16 [(size_t)MDEC*OUT_];  // decw^T (9600, 256) fp16
__device__ unsigned g_barArr;

__global__ void reset_bar_k() { g_barArr = 0u; }

__device__ __forceinline__ float tanh_fast(float x) {
    float y; asm("tanh.approx.f32 %0, %1;" : "=f"(y) : "f"(x)); return y;
}
__device__ __forceinline__ float sigm(float x) {
    return fmaf(0.5f, tanh_fast(0.5f * x), 0.5f);
}
__device__ __forceinline__ ull pack2(float lo, float hi) {
    ull r; asm("mov.b64 %0, {%1, %2};" : "=l"(r) : "f"(lo), "f"(hi)); return r;
}
__device__ __forceinline__ void unpack2(ull v, float& lo, float& hi) {
    asm("mov.b64 {%0, %1}, %2;" : "=f"(lo), "=f"(hi) : "l"(v));
}
__device__ __forceinline__ void fma2(ull& d, ull a, ull b) {
    asm("fma.rn.f32x2 %0, %1, %2, %0;" : "+l"(d) : "l"(a), "l"(b));
}
__device__ __forceinline__ void mma16816(float* c, const uint32_t* a, const uint32_t* b) {
    asm volatile(
        "mma.sync.aligned.m16n8k16.row.col.f32.f16.f16.f32 "
        "{%0,%1,%2,%3}, {%4,%5,%6,%7}, {%8,%9}, {%0,%1,%2,%3};"
        : "+f"(c[0]), "+f"(c[1]), "+f"(c[2]), "+f"(c[3])
        : "r"(a[0]), "r"(a[1]), "r"(a[2]), "r"(a[3]), "r"(b[0]), "r"(b[1]));
}

// ================= HMMA fp16 FF GEMM (proven) =================
#define SROW 136

__global__ __launch_bounds__(256) void hmma_gemm(
    const __half* __restrict__ Wt,
    const __half* __restrict__ Xbk,
    __half* __restrict__ XT)
{
    extern __shared__ __half sm[];
    __half* As = sm;
    __half* Bs = sm + 128 * SROW;

    const int t  = blockIdx.z;
    const int n0 = blockIdx.y * 128;
    const int b0 = blockIdx.x * 128;
    const int tid = threadIdx.x;
    const int wid = tid >> 5, lane = tid & 31;
    const int wm = wid >> 1;
    const int wn = wid & 1;

    {
        const float4* Ag = (const float4*)(Wt + (size_t)n0 * 128);
        const float4* Bg = (const float4*)(Xbk + ((size_t)t * BSZ + b0) * 128);
#pragma unroll
        for (int it = 0; it < 8; it++) {
            int i = tid + 256 * it;
            int r = i >> 4, c8 = (i & 15) * 8;
            *(float4*)&As[r * SROW + c8] = Ag[i];
            *(float4*)&Bs[r * SROW + c8] = Bg[i];
        }
    }
    __syncthreads();

    float acc[2][8][4];
#pragma unroll
    for (int mt = 0; mt < 2; mt++)
#pragma unroll
        for (int nt = 0; nt < 8; nt++)
#pragma unroll
            for (int e = 0; e < 4; e++) acc[mt][nt][e] = 0.f;

    const int fr = lane >> 2;
    const int kp = (lane & 3) * 2;

#pragma unroll
    for (int ks = 0; ks < 8; ks++) {
        const int k0 = ks * 16;
        uint32_t a[2][4];
#pragma unroll
        for (int mt = 0; mt < 2; mt++) {
            const int mr = wm * 32 + mt * 16;
            a[mt][0] = *(const uint32_t*)&As[(mr + fr)     * SROW + k0 + kp];
            a[mt][1] = *(const uint32_t*)&As[(mr + fr + 8) * SROW + k0 + kp];
            a[mt][2] = *(const uint32_t*)&As[(mr + fr)     * SROW + k0 + kp + 8];
            a[mt][3] = *(const uint32_t*)&As[(mr + fr + 8) * SROW + k0 + kp + 8];
        }
#pragma unroll
        for (int nt = 0; nt < 8; nt++) {
            const int bc = wn * 64 + nt * 8 + fr;
            uint32_t b[2];
            b[0] = *(const uint32_t*)&Bs[bc * SROW + k0 + kp];
            b[1] = *(const uint32_t*)&Bs[bc * SROW + k0 + kp + 8];
            mma16816(acc[0][nt], a[0], b);
            mma16816(acc[1][nt], a[1], b);
        }
    }

#pragma unroll
    for (int mt = 0; mt < 2; mt++) {
        const int n = n0 + wm * 32 + mt * 16 + fr;
        __half* R0 = XT + ((size_t)t * G4_ + n)     * BSZ + b0;
        __half* R1 = XT + ((size_t)t * G4_ + n + 8) * BSZ + b0;
#pragma unroll
        for (int nt = 0; nt < 8; nt++) {
            const int bcol = wn * 64 + nt * 8 + (lane & 3) * 2;
            *(__half2*)&R0[bcol] = __floats2half2_rn(acc[mt][nt][0], acc[mt][nt][1]);
            *(__half2*)&R1[bcol] = __floats2half2_rn(acc[mt][nt][2], acc[mt][nt][3]);
        }
    }
}

// ================= generic HMMA fp16 GEMM (fc + decoder head) =================
// C[i][j] = sum_k A16[i*K+k] * B16[j*K+k] + bias_c[j].  K in {128, 256}.
// out_half: write fp16 (for fc feeding decoder); else fp32.
__global__ __launch_bounds__(256) void hgemm16(
    const __half* __restrict__ A16, const __half* __restrict__ B16,
    void* __restrict__ Cout, int K, int Ncols,
    const float* __restrict__ bias_c, int out_half)
{
    extern __shared__ __half sm[];
    __half* As = sm;
    __half* Bs = sm + 128 * SROW;

    const int n0 = blockIdx.y * 128;   // output rows (A rows)
    const int b0 = blockIdx.x * 128;   // output cols (B rows)
    const int tid = threadIdx.x;
    const int wid = tid >> 5, lane = tid & 31;
    const int wm = wid >> 1;
    const int wn = wid & 1;
    const int fr = lane >> 4 ? 0 : 0;  // placeholder (avoid unused warn pattern)
    const int frr = lane >> 2;
    const int kp = (lane & 3) * 2;
    (void)fr;

    float acc[2][8][4];
#pragma unroll
    for (int mt = 0; mt < 2; mt++)
#pragma unroll
        for (int nt = 0; nt < 8; nt++)
#pragma unroll
            for (int e = 0; e < 4; e++) acc[mt][nt][e] = 0.f;

    const int kf4 = K / 8;             // float4 per row

    for (int kc = 0; kc < K; kc += 128) {
        const float4* Ag = (const float4*)(A16 + (size_t)n0 * K + kc);
        const float4* Bg = (const float4*)(B16 + (size_t)b0 * K + kc);
#pragma unroll
        for (int it = 0; it < 8; it++) {
            int i = tid + 256 * it;
            int r = i >> 4, c4 = i & 15;
            *(float4*)&As[r * SROW + c4 * 8] = Ag[(size_t)r * kf4 + c4];
            *(float4*)&Bs[r * SROW + c4 * 8] = Bg[(size_t)r * kf4 + c4];
        }
        __syncthreads();
#pragma unroll
        for (int ks = 0; ks < 8; ks++) {
            const int k0 = ks * 16;
            uint32_t a[2][4];
#pragma unroll
            for (int mt = 0; mt < 2; mt++) {
                const int mr = wm * 32 + mt * 16;
                a[mt][0] = *(const uint32_t*)&As[(mr + frr)     * SROW + k0 + kp];
                a[mt][1] = *(const uint32_t*)&As[(mr + frr + 8) * SROW + k0 + kp];
                a[mt][2] = *(const uint32_t*)&As[(mr + frr)     * SROW + k0 + kp + 8];
                a[mt][3] = *(const uint32_t*)&As[(mr + frr + 8) * SROW + k0 + kp + 8];
            }
#pragma unroll
            for (int nt = 0; nt < 8; nt++) {
                const int bc = wn * 64 + nt * 8 + frr;
                uint32_t b[2];
                b[0] = *(const uint32_t*)&Bs[bc * SROW + k0 + kp];
                b[1] = *(const uint32_t*)&Bs[bc * SROW + k0 + kp + 8];
                mma16816(acc[0][nt], a[0], b);
                mma16816(acc[1][nt], a[1], b);
            }
        }
        __syncthreads();
    }

#pragma unroll
    for (int mt = 0; mt < 2; mt++) {
        const int n = n0 + wm * 32 + mt * 16 + frr;
#pragma unroll
        for (int nt = 0; nt < 8; nt++) {
            const int bcol = b0 + wn * 64 + nt * 8 + (lane & 3) * 2;
            const float bz0 = bias_c ? bias_c[bcol] : 0.f;
            const float bz1 = bias_c ? bias_c[bcol + 1] : 0.f;
            if (out_half) {
                __half* C = (__half*)Cout;
                *(__half2*)&C[(size_t)n * Ncols + bcol] =
                    __floats2half2_rn(acc[mt][nt][0] + bz0, acc[mt][nt][1] + bz1);
                *(__half2*)&C[(size_t)(n + 8) * Ncols + bcol] =
                    __floats2half2_rn(acc[mt][nt][2] + bz0, acc[mt][nt][3] + bz1);
            } else {
                float* C = (float*)Cout;
                *(float2*)&C[(size_t)n * Ncols + bcol] =
                    make_float2(acc[mt][nt][0] + bz0, acc[mt][nt][1] + bz1);
                *(float2*)&C[(size_t)(n + 8) * Ncols + bcol] =
                    make_float2(acc[mt][nt][2] + bz0, acc[mt][nt][3] + bz1);
            }
        }
    }
}

// ---------------- operand prep kernels ----------------
__global__ __launch_bounds__(256) void w_to_t(const float* __restrict__ W,
                                              __half* __restrict__ Wt, int K)
{
    int i = blockIdx.x * 256 + threadIdx.x;
    int n = i >> 7, k = i & 127;
    Wt[i] = __float2half(k < K ? W[(size_t)k * G4_ + n] : 0.f);
}

__global__ __launch_bounds__(256) void x_to_bk(const float* __restrict__ seq,
                                               __half* __restrict__ xbk)
{
    int t = blockIdx.y;
    size_t i = (size_t)blockIdx.x * 256 + threadIdx.x;
    int b = (int)(i >> 7), k = (int)(i & 127);
    float v = (k < IN_) ? seq[((size_t)b * T_ + t) * IN_ + k] : 0.f;
    xbk[(size_t)t * BSZ * 128 + i] = __float2half(v);
}

__global__ __launch_bounds__(256) void h_to_bk(const float* __restrict__ hsT,
                                               __half* __restrict__ hbk)
{
    int t = blockIdx.z;
    int h0 = blockIdx.y * 32;
    int b0 = blockIdx.x * 32;
    __shared__ float sm[32][33];
    int tid = threadIdx.x;
    int lx = tid & 31, ly = tid >> 5;
#pragma unroll
    for (int i = 0; i < 4; i++) {
        int h = h0 + ly + i * 8;
        sm[ly + i * 8][lx] = hsT[((size_t)t * H_ + h) * BSZ + b0 + lx];
    }
    __syncthreads();
#pragma unroll
    for (int i = 0; i < 4; i++) {
        int b = b0 + ly + i * 8;
        hbk[((size_t)t * BSZ + b) * 128 + h0 + lx] = __float2half(sm[lx][ly + i * 8]);
    }
}

// (R, C) fp32 -> (C, R) fp16 tiled transpose
__global__ __launch_bounds__(256) void t32(const float* __restrict__ in,
                                           __half* __restrict__ out, int R, int C)
{
    __shared__ float sm[32][33];
    int r0 = blockIdx.y * 32, c0 = blockIdx.x * 32;
    int tid = threadIdx.x;
    int lx = tid & 31, ly = tid >> 5;
#pragma unroll
    for (int i = 0; i < 4; i++) {
        int r = r0 + ly + i * 8;
        sm[ly + i * 8][lx] = in[(size_t)r * C + c0 + lx];
    }
    __syncthreads();
#pragma unroll
    for (int i = 0; i < 4; i++) {
        int c = c0 + ly + i * 8;
        out[(size_t)c * R + r0 + lx] = __float2half(sm[lx][ly + i * 8]);
    }
}

// ---------------- per-(t,n) BN stats: one WARP per column ----------------
__global__ __launch_bounds__(256) void x_stats(const __half* __restrict__ XT,
                                               const float* __restrict__ gih,
                                               const float* __restrict__ bih,
                                               const float* __restrict__ bgate,
                                               const float* __restrict__ bhh,
                                               float* __restrict__ xsA,
                                               float* __restrict__ xsB)
{
    const int wid = threadIdx.x >> 5, lane = threadIdx.x & 31;
    const size_t idx = (size_t)blockIdx.x * 8 + wid;
    const uint4* col = (const uint4*)(XT + idx * BSZ);
    float s = 0.f, q = 0.f;
#pragma unroll
    for (int i = 0; i < 4; i++) {
        uint4 v = col[lane + 32 * i];
        const __half2* hp = (const __half2*)&v;
#pragma unroll
        for (int j = 0; j < 4; j++) {
            float2 f = __half22float2(hp[j]);
            s += f.x + f.y;
            q += f.x * f.x + f.y * f.y;
        }
    }
#pragma unroll
    for (int o = 16; o > 0; o >>= 1) {
        s += __shfl_down_sync(0xffffffffu, s, o);
        q += __shfl_down_sync(0xffffffffu, q, o);
    }
    if (lane == 0) {
        float m = s * (1.f / BSZ);
        float var = q * (1.f / BSZ) - m * m;
        float r = rsqrtf(var + EPS_);
        int n = (int)(idx & (G4_ - 1));
        xsA[idx] = gih[n] * r;
        xsB[idx] = bih[n] - gih[n] * r * m + bgate[n] + bhh[n];
    }
}

// ---------------- persistent fused BN-LSTM layer (round-8 exact) ----------------
__global__ __launch_bounds__(NTHR, 1) void bnlstm_layer(
    const __half* __restrict__ XT,
    const float* __restrict__ xsA,
    const float* __restrict__ xsB,
    const float* __restrict__ Whh,
    const float* __restrict__ ghh,
    const float* __restrict__ gc,
    const float* __restrict__ bc,
    float* __restrict__ hsOut,
    __half* __restrict__ h16,
    unsigned barBase)
{
    const int j = blockIdx.x;
    const int tid = threadIdx.x;
    const int lane = tid & 31, wid = tid >> 5;
    const int b0 = tid * 2;

    __shared__ float4 WhhS4[128];
    __shared__ float red[16][8];
    __shared__ float stat[8];

    {
        float* WhhS = (float*)WhhS4;
        WhhS[tid] = Whh[(size_t)(tid >> 2) * G4_ + j + H_ * (tid & 3)];
    }
    float ghq[4];
#pragma unroll
    for (int q = 0; q < 4; q++) ghq[q] = ghh[j + H_ * q];
    const float gcj = gc[j], bcj = bc[j];
    __syncthreads();

    float cc0 = 0.f, cc1 = 0.f;
    unsigned barTarget = barBase;

    float2 xv[4];
    float xa[4], xb[4];
#pragma unroll
    for (int q = 0; q < 4; q++) {
        const int n = j + H_ * q;
        xv[q] = __half22float2(*(const __half2*)&XT[(size_t)n * BSZ + b0]);
        xa[q] = xsA[n];
        xb[q] = xsB[n];
    }

    for (int t = 0; t < T_; t++) {
        float gate[4][2];
        if (t == 0) {
#pragma unroll
            for (int q = 0; q < 4; q++) {
                gate[q][0] = fmaf(xa[q], xv[q].x, xb[q]);
                gate[q][1] = fmaf(xa[q], xv[q].y, xb[q]);
            }
        } else {
            const __half* hp = h16 + (size_t)((t - 1) & 1) * H_ * BSZ + b0;
            ull aP01_0 = 0ull, aP23_0 = 0ull;
            ull aP01_1 = 0ull, aP23_1 = 0ull;
#pragma unroll 8
            for (int k = 0; k < H_; k++) {
                const __half2 hraw = *(const __half2*)&hp[(size_t)k * BSZ];
                const float2 hf = __half22float2(hraw);
                const float4 wv = WhhS4[k];
                const ull w01 = pack2(wv.x, wv.y);
                const ull w23 = pack2(wv.z, wv.w);
                const ull h0d = pack2(hf.x, hf.x);
                const ull h1d = pack2(hf.y, hf.y);
                fma2(aP01_0, w01, h0d);
                fma2(aP23_0, w23, h0d);
                fma2(aP01_1, w01, h1d);
                fma2(aP23_1, w23, h1d);
            }
            float acc[4][2];
            unpack2(aP01_0, acc[0][0], acc[1][0]);
            unpack2(aP23_0, acc[2][0], acc[3][0]);
            unpack2(aP01_1, acc[0][1], acc[1][1]);
            unpack2(aP23_1, acc[2][1], acc[3][1]);

            float vals[8];
#pragma unroll
            for (int q = 0; q < 4; q++) {
                vals[q]     = acc[q][0] + acc[q][1];
                vals[4 + q] = acc[q][0]*acc[q][0] + acc[q][1]*acc[q][1];
            }
#pragma unroll
            for (int v = 0; v < 8; v++) {
                float x = vals[v];
#pragma unroll
                for (int o = 16; o > 0; o >>= 1) x += __shfl_down_sync(0xffffffffu, x, o);
                if (lane == 0) red[wid][v] = x;
            }
            __syncthreads();
            if (tid < 8) {
                float s = 0.f;
#pragma unroll
                for (int w = 0; w < 16; w++) s += red[w][tid];
                stat[tid] = s;
            }
            __syncthreads();
#pragma unroll
            for (int q = 0; q < 4; q++) {
                const float m   = stat[q] * (1.f / BSZ);
                const float var = stat[4 + q] * (1.f / BSZ) - m * m;
                const float gr  = ghq[q] * rsqrtf(var + EPS_);
                gate[q][0] = fmaf(xa[q], xv[q].x, xb[q]) + gr * (acc[q][0] - m);
                gate[q][1] = fmaf(xa[q], xv[q].y, xb[q]) + gr * (acc[q][1] - m);
            }
        }

        cc0 = sigm(gate[0][0]) * cc0 + sigm(gate[1][0]) * tanh_fast(gate[3][0]);
        cc1 = sigm(gate[0][1]) * cc1 + sigm(gate[1][1]) * tanh_fast(gate[3][1]);
        float cs = cc0 + cc1;
        float cq = cc0 * cc0 + cc1 * cc1;
#pragma unroll
        for (int o = 16; o > 0; o >>= 1) {
            cs += __shfl_down_sync(0xffffffffu, cs, o);
            cq += __shfl_down_sync(0xffffffffu, cq, o);
        }
        __syncthreads();
        if (lane == 0) { red[wid][0] = cs; red[wid][1] = cq; }
        __syncthreads();
        if (tid < 2) {
            float s = 0.f;
#pragma unroll
            for (int w = 0; w < 16; w++) s += red[w][tid];
            stat[tid] = s;
        }
        __syncthreads();

        const float mc = stat[0] * (1.f / BSZ);
        const float rc = rsqrtf(stat[1] * (1.f / BSZ) - mc * mc + EPS_);
        float2 hv;
        hv.x = sigm(gate[2][0]) * tanh_fast(fmaf(gcj * rc, cc0 - mc, bcj));
        hv.y = sigm(gate[2][1]) * tanh_fast(fmaf(gcj * rc, cc1 - mc, bcj));
        *(float2*)&hsOut[(size_t)t * H_ * BSZ + (size_t)j * BSZ + b0] = hv;
        __half2 hh = __floats2half2_rn(hv.x, hv.y);
        *(__half2*)&h16[(size_t)(t & 1) * H_ * BSZ + (size_t)j * BSZ + b0] = hh;

        if (t < T_ - 1) {
            const __half* XtN = XT + (size_t)(t + 1) * G4_ * BSZ;
            const float* xsAN = xsA + (size_t)(t + 1) * G4_;
            const float* xsBN = xsB + (size_t)(t + 1) * G4_;
#pragma unroll
            for (int q = 0; q < 4; q++) {
                const int n = j + H_ * q;
                xv[q] = __half22float2(*(const __half2*)&XtN[(size_t)n * BSZ + b0]);
                xa[q] = xsAN[n];
                xb[q] = xsBN[n];
            }
            __syncthreads();
            barTarget += NBLK;
            if (tid == 0) {
                __threadfence();
                atomicAdd(&g_barArr, 1u);
                while (*((volatile unsigned*)&g_barArr) < barTarget) __nanosleep(64);
                __threadfence();
            }
            __syncthreads();
        }
    }
}

// ---------------- launch ----------------
extern "C" void kernel_launch(void* const* d_in, const int* in_sizes, int n_in,
                              void* d_out, int out_size)
{
    const float* seq  = (const float*)d_in[0];
    const float* Wih0 = (const float*)d_in[1];
    const float* Whh0 = (const float*)d_in[2];
    const float* b0   = (const float*)d_in[3];
    const float* gih0 = (const float*)d_in[4];
    const float* bih0 = (const float*)d_in[5];
    const float* ghh0 = (const float*)d_in[6];
    const float* bhh0 = (const float*)d_in[7];
    const float* gc0  = (const float*)d_in[8];
    const float* bc0  = (const float*)d_in[9];
    const float* Wih1 = (const float*)d_in[10];
    const float* Whh1 = (const float*)d_in[11];
    const float* b1   = (const float*)d_in[12];
    const float* gih1 = (const float*)d_in[13];
    const float* bih1 = (const float*)d_in[14];
    const float* ghh1 = (const float*)d_in[15];
    const float* bhh1 = (const float*)d_in[16];
    const float* gc1  = (const float*)d_in[17];
    const float* bc1  = (const float*)d_in[18];
    const float* fcw  = (const float*)d_in[19];
    const float* fcb  = (const float*)d_in[20];
    const float* decw = (const float*)d_in[21];
    const float* decb = (const float*)d_in[22];
    float* out = (float*)d_out;
    (void)in_sizes; (void)n_in; (void)out_size;

    __half *XT, *xbk, *hbk, *Wt, *h16, *emb16, *fw16, *dw16;
    float *hs0T, *hs1T, *xsA, *xsB;
    cudaGetSymbolAddress((void**)&XT,    g_XT);
    cudaGetSymbolAddress((void**)&xbk,   g_xbk);
    cudaGetSymbolAddress((void**)&hbk,   g_hbk);
    cudaGetSymbolAddress((void**)&Wt,    g_Wt);
    cudaGetSymbolAddress((void**)&h16,   g_h16);
    cudaGetSymbolAddress((void**)&hs0T,  g_hs0T);
    cudaGetSymbolAddress((void**)&hs1T,  g_hs1T);
    cudaGetSymbolAddress((void**)&xsA,   g_xsA);
    cudaGetSymbolAddress((void**)&xsB,   g_xsB);
    cudaGetSymbolAddress((void**)&emb16, g_emb16);
    cudaGetSymbolAddress((void**)&fw16,  g_fw16);
    cudaGetSymbolAddress((void**)&dw16,  g_dw16);

    const int HMMA_SMEM = 2 * 128 * SROW * (int)sizeof(__half);
    static int attr_set = 0;
    if (!attr_set) {
        cudaFuncSetAttribute(hmma_gemm, cudaFuncAttributeMaxDynamicSharedMemorySize, HMMA_SMEM);
        cudaFuncSetAttribute(hgemm16,   cudaFuncAttributeMaxDynamicSharedMemorySize, HMMA_SMEM);
        attr_set = 1;
    }

    reset_bar_k<<<1, 1>>>();

    // ---- layer 0 ----
    x_to_bk<<<dim3(BSZ * 128 / 256, T_), 256>>>(seq, xbk);
    w_to_t<<<G4_ * 128 / 256, 256>>>(Wih0, Wt, IN_);
    hmma_gemm<<<dim3(BSZ / 128, G4_ / 128, T_), 256, HMMA_SMEM>>>(Wt, xbk, XT);
    x_stats<<<T_ * G4_ / 8, 256>>>(XT, gih0, bih0, b0, bhh0, xsA, xsB);
    bnlstm_layer<<<NBLK, NTHR>>>(XT, xsA, xsB, Whh0, ghh0, gc0, bc0, hs0T, h16, 0u);

    // ---- layer 1 ----
    h_to_bk<<<dim3(BSZ / 32, H_ / 32, T_), 256>>>(hs0T, hbk);
    w_to_t<<<G4_ * 128 / 256, 256>>>(Wih1, Wt, H_);
    hmma_gemm<<<dim3(BSZ / 128, G4_ / 128, T_), 256, HMMA_SMEM>>>(Wt, hbk, XT);
    x_stats<<<T_ * G4_ / 8, 256>>>(XT, gih1, bih1, b1, bhh1, xsA, xsB);
    bnlstm_layer<<<NBLK, NTHR>>>(XT, xsA, xsB, Whh1, ghh1, gc1, bc1, hs1T, h16,
                                 (unsigned)((T_ - 1) * NBLK));

    // ---- head (HMMA fp16) ----
    // h_last (H,B) fp32 -> hbk (B,128) fp16 k-contig
    h_to_bk<<<dim3(BSZ / 32, H_ / 32, 1), 256>>>(hs1T + (size_t)(T_ - 1) * H_ * BSZ, hbk);
    // fcw (128,256) -> fw16 (256,128); decw (256,9600) -> dw16 (9600,256)
    t32<<<dim3(OUT_ / 32, H_ / 32), 256>>>(fcw, fw16, H_, OUT_);
    t32<<<dim3(MDEC / 32, OUT_ / 32), 256>>>(decw, dw16, OUT_, MDEC);
    // fc: emb16 (1024, 256) fp16
    hgemm16<<<dim3(OUT_ / 128, BSZ / 128), 256, HMMA_SMEM>>>(hbk, fw16, emb16,
                                                             H_, OUT_, fcb, 1);
    // decoder: out (1024, 9600) fp32
    hgemm16<<<dim3(MDEC / 128, BSZ / 128), 256, HMMA_SMEM>>>(emb16, dw16, out,
                                                             OUT_, MDEC, decb, 0);
}

// round 17
// speedup vs baseline: 1.6713x; 1.0160x over previous
#include <cuda_runtime.h>
#include <cuda_fp16.h>
#include <math.h>
#include <stdint.h>

#define T_    128
#define BSZ   1024
#define IN_   75
#define H_    128
#define G4_   512
#define OUT_  256
#define MDEC  (128*75)
#define EPS_  1e-5f
#define NBLK  128
#define NTHR  512

typedef unsigned long long ull;

// ---------------- device scratch ----------------
__device__ __half g_XT  [(size_t)T_*G4_*BSZ];  // (T, 4H, B) fp16 gate pre-activations
__device__ __half g_xbk [(size_t)T_*BSZ*128];  // (T, B, 128) fp16 padded input, k-contig
__device__ __half g_hbk [(size_t)T_*BSZ*128];  // (T, B, 128) fp16 hs0 transposed, k-contig
__device__ __half g_Wt  [(size_t)G4_*128];     // (512, 128) fp16 W^T k-contig
__device__ float  g_hs0T[(size_t)T_*H_*BSZ];
__device__ float  g_hs1T[(size_t)T_*H_*BSZ];
__device__ __half g_h16 [(size_t)2*H_*BSZ];    // ping-pong fp16 recurrent h
__device__ __half g_emb16[(size_t)BSZ*OUT_];   // fc output (B, 256) k-contig fp16
__device__ __half g_fw16 [(size_t)OUT_*H_];    // fcw^T (256, 128) fp16
__device__ __half g_dw16 [(size_t)MDEC*OUT_];  // decw^T (9600, 256) fp16
__device__ unsigned g_barArr;

__global__ void reset_bar_k() { g_barArr = 0u; }

__device__ __forceinline__ float tanh_fast(float x) {
    float y; asm("tanh.approx.f32 %0, %1;" : "=f"(y) : "f"(x)); return y;
}
__device__ __forceinline__ float sigm(float x) {
    return fmaf(0.5f, tanh_fast(0.5f * x), 0.5f);
}
__device__ __forceinline__ ull pack2(float lo, float hi) {
    ull r; asm("mov.b64 %0, {%1, %2};" : "=l"(r) : "f"(lo), "f"(hi)); return r;
}
__device__ __forceinline__ void unpack2(ull v, float& lo, float& hi) {
    asm("mov.b64 {%0, %1}, %2;" : "=f"(lo), "=f"(hi) : "l"(v));
}
__device__ __forceinline__ void fma2(ull& d, ull a, ull b) {
    asm("fma.rn.f32x2 %0, %1, %2, %0;" : "+l"(d) : "l"(a), "l"(b));
}
__device__ __forceinline__ void mma16816(float* c, const uint32_t* a, const uint32_t* b) {
    asm volatile(
        "mma.sync.aligned.m16n8k16.row.col.f32.f16.f16.f32 "
        "{%0,%1,%2,%3}, {%4,%5,%6,%7}, {%8,%9}, {%0,%1,%2,%3};"
        : "+f"(c[0]), "+f"(c[1]), "+f"(c[2]), "+f"(c[3])
        : "r"(a[0]), "r"(a[1]), "r"(a[2]), "r"(a[3]), "r"(b[0]), "r"(b[1]));
}

// ================= HMMA fp16 FF GEMM: 128 gates x 256 batch per block =================
#define SROW 136

__global__ __launch_bounds__(256) void hmma_gemm(
    const __half* __restrict__ Wt,
    const __half* __restrict__ Xbk,
    __half* __restrict__ XT)
{
    extern __shared__ __half sm[];
    __half* As = sm;                   // 128 x SROW
    __half* Bs = sm + 128 * SROW;      // 256 x SROW

    const int t  = blockIdx.z;
    const int n0 = blockIdx.y * 128;
    const int b0 = blockIdx.x * 256;
    const int tid = threadIdx.x;
    const int wid = tid >> 5, lane = tid & 31;
    const int wm = wid >> 1;
    const int wn = wid & 1;

    {
        const float4* Ag = (const float4*)(Wt + (size_t)n0 * 128);
        const float4* Bg = (const float4*)(Xbk + ((size_t)t * BSZ + b0) * 128);
#pragma unroll
        for (int it = 0; it < 8; it++) {
            int i = tid + 256 * it;
            int r = i >> 4, c8 = (i & 15) * 8;
            *(float4*)&As[r * SROW + c8] = Ag[i];
        }
#pragma unroll
        for (int it = 0; it < 16; it++) {
            int i = tid + 256 * it;
            int r = i >> 4, c8 = (i & 15) * 8;
            *(float4*)&Bs[r * SROW + c8] = Bg[i];
        }
    }
    __syncthreads();

    const int fr = lane >> 2;
    const int kp = (lane & 3) * 2;

#pragma unroll
    for (int nh = 0; nh < 2; nh++) {
        float acc[2][8][4];
#pragma unroll
        for (int mt = 0; mt < 2; mt++)
#pragma unroll
            for (int nt = 0; nt < 8; nt++)
#pragma unroll
                for (int e = 0; e < 4; e++) acc[mt][nt][e] = 0.f;

#pragma unroll
        for (int ks = 0; ks < 8; ks++) {
            const int k0 = ks * 16;
            uint32_t a[2][4];
#pragma unroll
            for (int mt = 0; mt < 2; mt++) {
                const int mr = wm * 32 + mt * 16;
                a[mt][0] = *(const uint32_t*)&As[(mr + fr)     * SROW + k0 + kp];
                a[mt][1] = *(const uint32_t*)&As[(mr + fr + 8) * SROW + k0 + kp];
                a[mt][2] = *(const uint32_t*)&As[(mr + fr)     * SROW + k0 + kp + 8];
                a[mt][3] = *(const uint32_t*)&As[(mr + fr + 8) * SROW + k0 + kp + 8];
            }
#pragma unroll
            for (int nt = 0; nt < 8; nt++) {
                const int bc = nh * 128 + wn * 64 + nt * 8 + fr;
                uint32_t b[2];
                b[0] = *(const uint32_t*)&Bs[bc * SROW + k0 + kp];
                b[1] = *(const uint32_t*)&Bs[bc * SROW + k0 + kp + 8];
                mma16816(acc[0][nt], a[0], b);
                mma16816(acc[1][nt], a[1], b);
            }
        }

#pragma unroll
        for (int mt = 0; mt < 2; mt++) {
            const int n = n0 + wm * 32 + mt * 16 + fr;
            __half* R0 = XT + ((size_t)t * G4_ + n)     * BSZ + b0;
            __half* R1 = XT + ((size_t)t * G4_ + n + 8) * BSZ + b0;
#pragma unroll
            for (int nt = 0; nt < 8; nt++) {
                const int bcol = nh * 128 + wn * 64 + nt * 8 + (lane & 3) * 2;
                *(__half2*)&R0[bcol] = __floats2half2_rn(acc[mt][nt][0], acc[mt][nt][1]);
                *(__half2*)&R1[bcol] = __floats2half2_rn(acc[mt][nt][2], acc[mt][nt][3]);
            }
        }
    }
}

// ================= generic HMMA fp16 GEMM (fc + decoder head) =================
__global__ __launch_bounds__(256) void hgemm16(
    const __half* __restrict__ A16, const __half* __restrict__ B16,
    void* __restrict__ Cout, int K, int Ncols,
    const float* __restrict__ bias_c, int out_half)
{
    extern __shared__ __half sm[];
    __half* As = sm;
    __half* Bs = sm + 128 * SROW;

    const int n0 = blockIdx.y * 128;
    const int b0 = blockIdx.x * 128;
    const int tid = threadIdx.x;
    const int wid = tid >> 5, lane = tid & 31;
    const int wm = wid >> 1;
    const int wn = wid & 1;
    const int frr = lane >> 2;
    const int kp = (lane & 3) * 2;

    float acc[2][8][4];
#pragma unroll
    for (int mt = 0; mt < 2; mt++)
#pragma unroll
        for (int nt = 0; nt < 8; nt++)
#pragma unroll
            for (int e = 0; e < 4; e++) acc[mt][nt][e] = 0.f;

    const int kf4 = K / 8;

    for (int kc = 0; kc < K; kc += 128) {
        const float4* Ag = (const float4*)(A16 + (size_t)n0 * K + kc);
        const float4* Bg = (const float4*)(B16 + (size_t)b0 * K + kc);
#pragma unroll
        for (int it = 0; it < 8; it++) {
            int i = tid + 256 * it;
            int r = i >> 4, c4 = i & 15;
            *(float4*)&As[r * SROW + c4 * 8] = Ag[(size_t)r * kf4 + c4];
            *(float4*)&Bs[r * SROW + c4 * 8] = Bg[(size_t)r * kf4 + c4];
        }
        __syncthreads();
#pragma unroll
        for (int ks = 0; ks < 8; ks++) {
            const int k0 = ks * 16;
            uint32_t a[2][4];
#pragma unroll
            for (int mt = 0; mt < 2; mt++) {
                const int mr = wm * 32 + mt * 16;
                a[mt][0] = *(const uint32_t*)&As[(mr + frr)     * SROW + k0 + kp];
                a[mt][1] = *(const uint32_t*)&As[(mr + frr + 8) * SROW + k0 + kp];
                a[mt][2] = *(const uint32_t*)&As[(mr + frr)     * SROW + k0 + kp + 8];
                a[mt][3] = *(const uint32_t*)&As[(mr + frr + 8) * SROW + k0 + kp + 8];
            }
#pragma unroll
            for (int nt = 0; nt < 8; nt++) {
                const int bc = wn * 64 + nt * 8 + frr;
                uint32_t b[2];
                b[0] = *(const uint32_t*)&Bs[bc * SROW + k0 + kp];
                b[1] = *(const uint32_t*)&Bs[bc * SROW + k0 + kp + 8];
                mma16816(acc[0][nt], a[0], b);
                mma16816(acc[1][nt], a[1], b);
            }
        }
        __syncthreads();
    }

#pragma unroll
    for (int mt = 0; mt < 2; mt++) {
        const int n = n0 + wm * 32 + mt * 16 + frr;
#pragma unroll
        for (int nt = 0; nt < 8; nt++) {
            const int bcol = b0 + wn * 64 + nt * 8 + (lane & 3) * 2;
            const float bz0 = bias_c ? bias_c[bcol] : 0.f;
            const float bz1 = bias_c ? bias_c[bcol + 1] : 0.f;
            if (out_half) {
                __half* C = (__half*)Cout;
                *(__half2*)&C[(size_t)n * Ncols + bcol] =
                    __floats2half2_rn(acc[mt][nt][0] + bz0, acc[mt][nt][1] + bz1);
                *(__half2*)&C[(size_t)(n + 8) * Ncols + bcol] =
                    __floats2half2_rn(acc[mt][nt][2] + bz0, acc[mt][nt][3] + bz1);
            } else {
                float* C = (float*)Cout;
                *(float2*)&C[(size_t)n * Ncols + bcol] =
                    make_float2(acc[mt][nt][0] + bz0, acc[mt][nt][1] + bz1);
                *(float2*)&C[(size_t)(n + 8) * Ncols + bcol] =
                    make_float2(acc[mt][nt][2] + bz0, acc[mt][nt][3] + bz1);
            }
        }
    }
}

// ---------------- operand prep kernels ----------------
__global__ __launch_bounds__(256) void w_to_t(const float* __restrict__ W,
                                              __half* __restrict__ Wt, int K)
{
    int i = blockIdx.x * 256 + threadIdx.x;
    int n = i >> 7, k = i & 127;
    Wt[i] = __float2half(k < K ? W[(size_t)k * G4_ + n] : 0.f);
}

__global__ __launch_bounds__(256) void x_to_bk(const float* __restrict__ seq,
                                               __half* __restrict__ xbk)
{
    int t = blockIdx.y;
    size_t i = (size_t)blockIdx.x * 256 + threadIdx.x;
    int b = (int)(i >> 7), k = (int)(i & 127);
    float v = (k < IN_) ? seq[((size_t)b * T_ + t) * IN_ + k] : 0.f;
    xbk[(size_t)t * BSZ * 128 + i] = __float2half(v);
}

__global__ __launch_bounds__(256) void h_to_bk(const float* __restrict__ hsT,
                                               __half* __restrict__ hbk)
{
    int t = blockIdx.z;
    int h0 = blockIdx.y * 32;
    int b0 = blockIdx.x * 32;
    __shared__ float sm[32][33];
    int tid = threadIdx.x;
    int lx = tid & 31, ly = tid >> 5;
#pragma unroll
    for (int i = 0; i < 4; i++) {
        int h = h0 + ly + i * 8;
        sm[ly + i * 8][lx] = hsT[((size_t)t * H_ + h) * BSZ + b0 + lx];
    }
    __syncthreads();
#pragma unroll
    for (int i = 0; i < 4; i++) {
        int b = b0 + ly + i * 8;
        hbk[((size_t)t * BSZ + b) * 128 + h0 + lx] = __float2half(sm[lx][ly + i * 8]);
    }
}

// (R, C) fp32 -> (C, R) fp16 tiled transpose
__global__ __launch_bounds__(256) void t32(const float* __restrict__ in,
                                           __half* __restrict__ out, int R, int C)
{
    __shared__ float sm[32][33];
    int r0 = blockIdx.y * 32, c0 = blockIdx.x * 32;
    int tid = threadIdx.x;
    int lx = tid & 31, ly = tid >> 5;
#pragma unroll
    for (int i = 0; i < 4; i++) {
        int r = r0 + ly + i * 8;
        sm[ly + i * 8][lx] = in[(size_t)r * C + c0 + lx];
    }
    __syncthreads();
#pragma unroll
    for (int i = 0; i < 4; i++) {
        int c = c0 + ly + i * 8;
        out[(size_t)c * R + r0 + lx] = __float2half(sm[lx][ly + i * 8]);
    }
}

// ---------------- persistent fused BN-LSTM layer (x_stats fused in) ----------------
__global__ __launch_bounds__(NTHR, 1) void bnlstm_layer(
    const __half* __restrict__ XT,
    const float* __restrict__ gih,
    const float* __restrict__ bih,
    const float* __restrict__ bgate,
    const float* __restrict__ bhh,
    const float* __restrict__ Whh,
    const float* __restrict__ ghh,
    const float* __restrict__ gc,
    const float* __restrict__ bc,
    float* __restrict__ hsOut,
    __half* __restrict__ h16,
    unsigned barBase)
{
    const int j = blockIdx.x;
    const int tid = threadIdx.x;
    const int lane = tid & 31, wid = tid >> 5;
    const int b0 = tid * 2;

    __shared__ float4 WhhS4[128];
    __shared__ float red[16][16];
    __shared__ float stat[16];

    {
        float* WhhS = (float*)WhhS4;
        WhhS[tid] = Whh[(size_t)(tid >> 2) * G4_ + j + H_ * (tid & 3)];
    }
    float ghq[4], gihq[4], xbq[4];
#pragma unroll
    for (int q = 0; q < 4; q++) {
        const int n = j + H_ * q;
        ghq[q]  = ghh[n];
        gihq[q] = gih[n];
        xbq[q]  = bih[n] + bgate[n] + bhh[n];
    }
    const float gcj = gc[j], bcj = bc[j];
    __syncthreads();

    float cc0 = 0.f, cc1 = 0.f;
    unsigned barTarget = barBase;
    const float invB = 1.f / BSZ;

    float2 xv[4];
#pragma unroll
    for (int q = 0; q < 4; q++)
        xv[q] = __half22float2(*(const __half2*)&XT[(size_t)(j + H_ * q) * BSZ + b0]);

    for (int t = 0; t < T_; t++) {
        float acc[4][2];
        if (t == 0) {
#pragma unroll
            for (int q = 0; q < 4; q++) { acc[q][0] = 0.f; acc[q][1] = 0.f; }
        } else {
            const __half* hp = h16 + (size_t)((t - 1) & 1) * H_ * BSZ + b0;
            ull aP01_0 = 0ull, aP23_0 = 0ull;
            ull aP01_1 = 0ull, aP23_1 = 0ull;
#pragma unroll 8
            for (int k = 0; k < H_; k++) {
                const __half2 hraw = *(const __half2*)&hp[(size_t)k * BSZ];
                const float2 hf = __half22float2(hraw);
                const float4 wv = WhhS4[k];
                const ull w01 = pack2(wv.x, wv.y);
                const ull w23 = pack2(wv.z, wv.w);
                const ull h0d = pack2(hf.x, hf.x);
                const ull h1d = pack2(hf.y, hf.y);
                fma2(aP01_0, w01, h0d);
                fma2(aP23_0, w23, h0d);
                fma2(aP01_1, w01, h1d);
                fma2(aP23_1, w23, h1d);
            }
            unpack2(aP01_0, acc[0][0], acc[1][0]);
            unpack2(aP23_0, acc[2][0], acc[3][0]);
            unpack2(aP01_1, acc[0][1], acc[1][1]);
            unpack2(aP23_1, acc[2][1], acc[3][1]);
        }

        // combined reduction: gate-h stats (0..7) + x stats (8..15)
        float vals[16];
#pragma unroll
        for (int q = 0; q < 4; q++) {
            vals[q]      = acc[q][0] + acc[q][1];
            vals[4 + q]  = acc[q][0]*acc[q][0] + acc[q][1]*acc[q][1];
            vals[8 + q]  = xv[q].x + xv[q].y;
            vals[12 + q] = xv[q].x*xv[q].x + xv[q].y*xv[q].y;
        }
#pragma unroll
        for (int v = 0; v < 16; v++) {
            float x = vals[v];
#pragma unroll
            for (int o = 16; o > 0; o >>= 1) x += __shfl_down_sync(0xffffffffu, x, o);
            if (lane == 0) red[wid][v] = x;
        }
        __syncthreads();
        if (tid < 16) {
            float s = 0.f;
#pragma unroll
            for (int w = 0; w < 16; w++) s += red[w][tid];
            stat[tid] = s;
        }
        __syncthreads();

        float gate[4][2];
#pragma unroll
        for (int q = 0; q < 4; q++) {
            const float mx   = stat[8 + q] * invB;
            const float varx = stat[12 + q] * invB - mx * mx;
            const float xa   = gihq[q] * rsqrtf(varx + EPS_);
            const float xb   = xbq[q] - xa * mx;
            const float mh   = stat[q] * invB;
            const float varh = stat[4 + q] * invB - mh * mh;
            const float gr   = ghq[q] * rsqrtf(varh + EPS_);
            gate[q][0] = fmaf(xa, xv[q].x, xb) + gr * (acc[q][0] - mh);
            gate[q][1] = fmaf(xa, xv[q].y, xb) + gr * (acc[q][1] - mh);
        }

        cc0 = sigm(gate[0][0]) * cc0 + sigm(gate[1][0]) * tanh_fast(gate[3][0]);
        cc1 = sigm(gate[0][1]) * cc1 + sigm(gate[1][1]) * tanh_fast(gate[3][1]);
        float cs = cc0 + cc1;
        float cq = cc0 * cc0 + cc1 * cc1;
#pragma unroll
        for (int o = 16; o > 0; o >>= 1) {
            cs += __shfl_down_sync(0xffffffffu, cs, o);
            cq += __shfl_down_sync(0xffffffffu, cq, o);
        }
        __syncthreads();
        if (lane == 0) { red[wid][0] = cs; red[wid][1] = cq; }
        __syncthreads();
        if (tid < 2) {
            float s = 0.f;
#pragma unroll
            for (int w = 0; w < 16; w++) s += red[w][tid];
            stat[tid] = s;
        }
        __syncthreads();

        const float mc = stat[0] * invB;
        const float rc = rsqrtf(stat[1] * invB - mc * mc + EPS_);
        float2 hv;
        hv.x = sigm(gate[2][0]) * tanh_fast(fmaf(gcj * rc, cc0 - mc, bcj));
        hv.y = sigm(gate[2][1]) * tanh_fast(fmaf(gcj * rc, cc1 - mc, bcj));
        *(float2*)&hsOut[(size_t)t * H_ * BSZ + (size_t)j * BSZ + b0] = hv;
        __half2 hh = __floats2half2_rn(hv.x, hv.y);
        *(__half2*)&h16[(size_t)(t & 1) * H_ * BSZ + (size_t)j * BSZ + b0] = hh;

        if (t < T_ - 1) {
            __syncthreads();               // all h16 stores issued block-wide
            barTarget += NBLK;
            if (tid == 0) {
                __threadfence();
                atomicAdd(&g_barArr, 1u);  // arrive EARLY (before prefetch)
            }
            // prefetch t+1's x-side; overlaps other blocks' arrivals
            const __half* XtN = XT + (size_t)(t + 1) * G4_ * BSZ;
#pragma unroll
            for (int q = 0; q < 4; q++)
                xv[q] = __half22float2(*(const __half2*)&XtN[(size_t)(j + H_ * q) * BSZ + b0]);
            if (tid == 0) {
                while (*((volatile unsigned*)&g_barArr) < barTarget) __nanosleep(64);
                __threadfence();
            }
            __syncthreads();
        }
    }
}

// ---------------- launch ----------------
extern "C" void kernel_launch(void* const* d_in, const int* in_sizes, int n_in,
                              void* d_out, int out_size)
{
    const float* seq  = (const float*)d_in[0];
    const float* Wih0 = (const float*)d_in[1];
    const float* Whh0 = (const float*)d_in[2];
    const float* b0   = (const float*)d_in[3];
    const float* gih0 = (const float*)d_in[4];
    const float* bih0 = (const float*)d_in[5];
    const float* ghh0 = (const float*)d_in[6];
    const float* bhh0 = (const float*)d_in[7];
    const float* gc0  = (const float*)d_in[8];
    const float* bc0  = (const float*)d_in[9];
    const float* Wih1 = (const float*)d_in[10];
    const float* Whh1 = (const float*)d_in[11];
    const float* b1   = (const float*)d_in[12];
    const float* gih1 = (const float*)d_in[13];
    const float* bih1 = (const float*)d_in[14];
    const float* ghh1 = (const float*)d_in[15];
    const float* bhh1 = (const float*)d_in[16];
    const float* gc1  = (const float*)d_in[17];
    const float* bc1  = (const float*)d_in[18];
    const float* fcw  = (const float*)d_in[19];
    const float* fcb  = (const float*)d_in[20];
    const float* decw = (const float*)d_in[21];
    const float* decb = (const float*)d_in[22];
    float* out = (float*)d_out;
    (void)in_sizes; (void)n_in; (void)out_size;

    __half *XT, *xbk, *hbk, *Wt, *h16, *emb16, *fw16, *dw16;
    float *hs0T, *hs1T;
    cudaGetSymbolAddress((void**)&XT,    g_XT);
    cudaGetSymbolAddress((void**)&xbk,   g_xbk);
    cudaGetSymbolAddress((void**)&hbk,   g_hbk);
    cudaGetSymbolAddress((void**)&Wt,    g_Wt);
    cudaGetSymbolAddress((void**)&h16,   g_h16);
    cudaGetSymbolAddress((void**)&hs0T,  g_hs0T);
    cudaGetSymbolAddress((void**)&hs1T,  g_hs1T);
    cudaGetSymbolAddress((void**)&emb16, g_emb16);
    cudaGetSymbolAddress((void**)&fw16,  g_fw16);
    cudaGetSymbolAddress((void**)&dw16,  g_dw16);

    const int FF_SMEM   = (128 + 256) * SROW * (int)sizeof(__half);  // ~102 KB
    const int HEAD_SMEM = 2 * 128 * SROW * (int)sizeof(__half);      // ~68 KB
    static int attr_set = 0;
    if (!attr_set) {
        cudaFuncSetAttribute(hmma_gemm, cudaFuncAttributeMaxDynamicSharedMemorySize, FF_SMEM);
        cudaFuncSetAttribute(hgemm16,   cudaFuncAttributeMaxDynamicSharedMemorySize, HEAD_SMEM);
        attr_set = 1;
    }

    reset_bar_k<<<1, 1>>>();

    // ---- layer 0 ----
    x_to_bk<<<dim3(BSZ * 128 / 256, T_), 256>>>(seq, xbk);
    w_to_t<<<G4_ * 128 / 256, 256>>>(Wih0, Wt, IN_);
    hmma_gemm<<<dim3(BSZ / 256, G4_ / 128, T_), 256, FF_SMEM>>>(Wt, xbk, XT);
    bnlstm_layer<<<NBLK, NTHR>>>(XT, gih0, bih0, b0, bhh0, Whh0, ghh0, gc0, bc0,
                                 hs0T, h16, 0u);

    // ---- layer 1 ----
    h_to_bk<<<dim3(BSZ / 32, H_ / 32, T_), 256>>>(hs0T, hbk);
    w_to_t<<<G4_ * 128 / 256, 256>>>(Wih1, Wt, H_);
    hmma_gemm<<<dim3(BSZ / 256, G4_ / 128, T_), 256, FF_SMEM>>>(Wt, hbk, XT);
    bnlstm_layer<<<NBLK, NTHR>>>(XT, gih1, bih1, b1, bhh1, Whh1, ghh1, gc1, bc1,
                                 hs1T, h16, (unsigned)((T_ - 1) * NBLK));

    // ---- head (HMMA fp16) ----
    h_to_bk<<<dim3(BSZ / 32, H_ / 32, 1), 256>>>(hs1T + (size_t)(T_ - 1) * H_ * BSZ, hbk);
    t32<<<dim3(OUT_ / 32, H_ / 32), 256>>>(fcw, fw16, H_, OUT_);
    t32<<<dim3(MDEC / 32, OUT_ / 32), 256>>>(decw, dw16, OUT_, MDEC);
    hgemm16<<<dim3(OUT_ / 128, BSZ / 128), 256, HEAD_SMEM>>>(hbk, fw16, emb16,
                                                             H_, OUT_, fcb, 1);
    hgemm16<<<dim3(MDEC / 128, BSZ / 128), 256, HEAD_SMEM>>>(emb16, dw16, out,
                                                             OUT_, MDEC, decb, 0);
}